// round 7
// baseline (speedup 1.0000x reference)
#include <cuda_runtime.h>
#include <math.h>

#define N_CELLS 20
#define IN 8
#define HID 10
#define NGATES 800
#define FEAT 200
#define H1 50
#define H2 10

#define PITCH_IH 9     // odd pitch, coprime to 32
#define PITCH_HH 11    // odd pitch, coprime to 32

// Dynamic shared layout (float offsets)
#define OFF_WIH   0
#define OFF_WHH   (OFF_WIH + NGATES * PITCH_IH)    // 7200
#define OFF_X     (OFF_WHH + NGATES * PITCH_HH)    // 16000
#define OFF_H0    (OFF_X + IN)                     // 16008
#define OFF_FEAT  (OFF_H0 + FEAT)                  // 16208
#define OFF_H1    (OFF_FEAT + FEAT)                // 16408
#define OFF_W2    (OFF_H1 + H1)                    // 16458
#define SMEM_FLOATS (OFF_W2 + H2 * H1)             // 16958
#define SMEM_BYTES  (SMEM_FLOATS * 4)              // 67832

__device__ __forceinline__ float tanh_fast(float x) {
    float xc = fminf(fmaxf(x, -15.0f), 15.0f);
    float e = __expf(2.0f * xc);
    return __fdividef(e - 1.0f, e + 1.0f);
}
__device__ __forceinline__ float sigmoid_fast(float x) {
    float xc = fminf(fmaxf(x, -30.0f), 30.0f);
    return __fdividef(1.0f, 1.0f + __expf(-xc));
}

__global__ __launch_bounds__(800, 1)
void lstm_mlp_fused(const float* __restrict__ x,
                    const float* __restrict__ h0,
                    const float* __restrict__ c0,
                    const float* __restrict__ W_ih,
                    const float* __restrict__ W_hh,
                    const float* __restrict__ b_ih,
                    const float* __restrict__ b_hh,
                    const float* __restrict__ W1,
                    const float* __restrict__ b1,
                    const float* __restrict__ W2,
                    const float* __restrict__ b2,
                    const float* __restrict__ W3,
                    const float* __restrict__ b3,
                    float* __restrict__ out)
{
    extern __shared__ float sm[];
    const int t = threadIdx.x;
    const int lane   = t & 31;
    const int lane16 = t & 15;
    const int row16  = t >> 4;                 // stage-3 row 0..49

    // Gate-row mapping for merged stage 1+2:
    // warp w owns outputs o = 8w..8w+7; lane = 4q+g computes gate g of o=8w+q.
    const int o    = (t >> 5) * 8 + (lane >> 2);   // 0..199
    const int g    = lane & 3;
    const int cell = o / 10;
    const int j    = o - cell * 10;
    const int r    = cell * 40 + g * 10 + j;       // gate row 0..799

    // ================= Entry: coalesced global -> shared / registers =========
    float bias = b_ih[r] + b_hh[r];
    float c0r  = c0[o];

    // W_ih / W_hh: coalesced LDG, padded row-major STS
    #pragma unroll
    for (int k = 0; k < 8; ++k) {
        int q = t + 800 * k;                               // q < 6400
        sm[OFF_WIH + (q >> 3) * PITCH_IH + (q & 7)] = W_ih[q];
    }
    #pragma unroll
    for (int k = 0; k < 10; ++k) {
        int q = t + 800 * k;                               // q < 8000
        sm[OFF_WHH + (q / HID) * PITCH_HH + (q % HID)] = W_hh[q];
    }
    // W2 -> shared (coalesced)
    if (t < H2 * H1) sm[OFF_W2 + t] = W2[t];

    // Stage-3 operands: W1 row slice in registers, 16 lanes per row
    const float* w1p = W1 + row16 * FEAT + lane16;
    float w1r[12];
    #pragma unroll
    for (int u = 0; u < 12; ++u) w1r[u] = w1p[u << 4];
    float w1t = (lane16 < 8) ? w1p[192] : 0.0f;
    float b1r = (lane16 == 0) ? b1[row16] : 0.0f;

    // Stage-4/5 operands (warp 0 only)
    float b2r = 0.0f, w3r = 0.0f, b3r = 0.0f;
    if (t < H2) { b2r = b2[t]; w3r = W3[t]; }
    if (t == 0) b3r = b3[0];

    // Tiny shared vectors
    if (t < IN)   sm[OFF_X + t]  = x[t];
    if (t < FEAT) sm[OFF_H0 + t] = h0[t];
    __syncthreads();

    // ======== Stage 1+2 merged: gate dot + activation + cell update ==========
    {
        const float* wi = sm + OFF_WIH + r * PITCH_IH;
        const float* wh = sm + OFF_WHH + r * PITCH_HH;
        const float* xx = sm + OFF_X;
        const float* hr = sm + OFF_H0 + cell * HID;
        float acc = bias;
        #pragma unroll
        for (int i = 0; i < IN; ++i)  acc = fmaf(wi[i], xx[i], acc);
        #pragma unroll
        for (int k = 0; k < HID; ++k) acc = fmaf(wh[k], hr[k], acc);

        // gate activation: sigmoid for i,f,o (g!=2); tanh via 2*sig(2x)-1 for g==2
        float vin = (g == 2) ? (acc + acc) : acc;
        float s   = sigmoid_fast(vin);
        float act = (g == 2) ? fmaf(2.0f, s, -1.0f) : s;

        const int base = lane & ~3;
        float ia = __shfl_sync(0xffffffffu, act, base);
        float fa = __shfl_sync(0xffffffffu, act, base + 1);
        float ga = __shfl_sync(0xffffffffu, act, base + 2);
        float oa = __shfl_sync(0xffffffffu, act, base + 3);
        if (g == 0) {
            float c = fmaf(fa, c0r, ia * ga);
            float h = oa * tanh_fast(c);
            int fidx = (cell >= 10) ? (o - 100) : (o + 100);   // gen bank first
            sm[OFF_FEAT + fidx] = h;
        }
    }
    __syncthreads();

    // ======== Stage 3: h1 = tanh(W1 @ feat + b1), 16 lanes/row ===============
    {
        const float* f = sm + OFF_FEAT;
        float sum = 0.0f;
        #pragma unroll
        for (int u = 0; u < 12; ++u)
            sum = fmaf(w1r[u], f[lane16 + (u << 4)], sum);
        if (lane16 < 8)
            sum = fmaf(w1t, f[192 + lane16], sum);
        sum += __shfl_xor_sync(0xffffffffu, sum, 8);
        sum += __shfl_xor_sync(0xffffffffu, sum, 4);
        sum += __shfl_xor_sync(0xffffffffu, sum, 2);
        sum += __shfl_xor_sync(0xffffffffu, sum, 1);
        if (lane16 == 0) sm[OFF_H1 + row16] = tanh_fast(sum + b1r);
    }
    __syncthreads();

    // ======== Stage 4+5 fused in warp 0: h2 rows per lane, shuffle-reduce ====
    if (t < 32) {
        float sum = 0.0f;
        if (t < H2) {
            const float* wv = sm + OFF_W2 + t * H1;   // banks 18r mod 32: distinct
            const float* hv = sm + OFF_H1;            // broadcast reads
            #pragma unroll
            for (int i = 0; i < H1; ++i) sum = fmaf(wv[i], hv[i], sum);
        }
        float p = (t < H2) ? w3r * tanh_fast(sum + b2r) : 0.0f;
        #pragma unroll
        for (int m = 16; m > 0; m >>= 1)
            p += __shfl_xor_sync(0xffffffffu, p, m);
        if (t == 0) out[0] = tanh_fast(p + b3r);
    }
}

extern "C" void kernel_launch(void* const* d_in, const int* in_sizes, int n_in,
                              void* d_out, int out_size) {
    (void)in_sizes; (void)n_in; (void)out_size;
    const float* x    = (const float*)d_in[0];
    const float* h0   = (const float*)d_in[1];
    const float* c0   = (const float*)d_in[2];
    const float* W_ih = (const float*)d_in[3];
    const float* W_hh = (const float*)d_in[4];
    const float* b_ih = (const float*)d_in[5];
    const float* b_hh = (const float*)d_in[6];
    const float* W1   = (const float*)d_in[7];
    const float* b1   = (const float*)d_in[8];
    const float* W2   = (const float*)d_in[9];
    const float* b2   = (const float*)d_in[10];
    const float* W3   = (const float*)d_in[11];
    const float* b3   = (const float*)d_in[12];
    float* out = (float*)d_out;

    static bool attr_set = false;
    if (!attr_set) {
        cudaFuncSetAttribute(lstm_mlp_fused,
                             cudaFuncAttributeMaxDynamicSharedMemorySize,
                             SMEM_BYTES);
        attr_set = true;
    }

    lstm_mlp_fused<<<1, 800, SMEM_BYTES>>>(x, h0, c0, W_ih, W_hh, b_ih, b_hh,
                                           W1, b1, W2, b2, W3, b3, out);
}